// round 14
// baseline (speedup 1.0000x reference)
#include <cuda_runtime.h>
#include <math.h>

#define NQ 8
#define NS 256          // 2^8 amplitudes
#define DEPTH 200
#define BSZ 16384
#define NXF 64
#define NT 32           // batches per block in main kernel
#define NTP 33          // padded batch stride in shared
#define NBLK (BSZ/NT)   // 512 blocks

typedef unsigned long long ull;

// ---------------- device globals (no cudaMalloc allowed) ----------------
__device__ float4 g_uv[600 * 8];     // per layer/qubit: (u.re,u.im,v.re,v.im) of RY(b)*RX(a)
__device__ float2 g_encphi[128];     // (cos(phi/2), sin(phi/2)) for encode phi angles
__device__ float2 g_v0[NS];          // U1 |0>  (written by k_comb block 16)
__device__ float2 g_w1[NS];          // (block-1 layers 0..99) |0>
__device__ float2 g_S[5][NS * NS];   // segment columns [s][c*256+m];
                                     // s: 0=U2s1, 1=U2s2, 2=U3s1, 3=U3s2, 4=block1 s2
__device__ float2 g_WT[2][NS * NS];  // U'[m][k] stored [k*256+m]  (0=U2', 1=U3')

// ---------------- packed f32x2 helpers ----------------
__device__ __forceinline__ void ffma2(ull& d, ull a, ull b) {
    asm("fma.rn.f32x2 %0, %1, %2, %0;" : "+l"(d) : "l"(a), "l"(b));
}
__device__ __forceinline__ ull pack2(float lo, float hi) {
    ull r; asm("mov.b64 %0, {%1, %2};" : "=l"(r) : "f"(lo), "f"(hi)); return r;
}
__device__ __forceinline__ float2 unpack2(ull v) {
    float2 r; asm("mov.b64 {%0, %1}, %2;" : "=f"(r.x), "=f"(r.y) : "l"(v)); return r;
}

// ring-CZ parity sign for amplitude index n (qubit i <-> bit 7-i)
__device__ __forceinline__ float czsign(int n) {
    int par = __popc(n & (n >> 1)) + ((n & (n >> 7)) & 1);
    return (par & 1) ? -1.0f : 1.0f;
}

// ---------------- K0: angle tables ----------------
__global__ void k_tables(const float* __restrict__ phi) {
    int tid = blockIdx.x * blockDim.x + threadIdx.x;
    int stride = gridDim.x * blockDim.x;
    for (int idx = tid; idx < 600 * 8; idx += stride) {
        int L = idx >> 3, q = idx & 7;
        int base, l;
        if (L < 200)      { base = 0;    l = L; }
        else if (L < 400) { base = 3264; l = L - 200; }
        else              { base = 6528; l = L - 400; }
        float a = phi[base + l * 16 + q];
        float b = phi[base + l * 16 + 8 + q];
        float ca, sa, cb, sb;
        sincosf(0.5f * a, &sa, &ca);
        sincosf(0.5f * b, &sb, &cb);
        g_uv[idx] = make_float4(ca * cb, sa * sb, ca * sb, -sa * cb);
    }
    for (int idx = tid; idx < 128; idx += stride) {
        int base = (idx < 64) ? 3200 : 6400;
        float p = phi[base + idx];
        float c, s;
        sincosf(0.5f * p, &s, &c);
        g_encphi[idx] = make_float2(c, s);
    }
}

// ---------------- segment layer step (register/shuffle state machine) ----------------
__device__ __forceinline__ void seg_step(float2 amp[8], const float4 uvL[8],
                                         const float sgn[8], int lane, bool docz) {
    #pragma unroll
    for (int q = 0; q < 5; q++) {
        float4 uv = uvL[q];
        int b = 4 - q;
        int mybit = (lane >> b) & 1;
        float mai = mybit ? -uv.y : uv.y;
        float mbr = mybit ?  uv.z : -uv.z;
        ull Ap = pack2(uv.x, mai),  An = pack2(-mai, uv.x);
        ull Bp = pack2(mbr, uv.w),  Bn = pack2(-uv.w, mbr);
        #pragma unroll
        for (int j = 0; j < 8; j++) {
            float pr = __shfl_xor_sync(0xffffffffu, amp[j].x, 1 << b);
            float pi = __shfl_xor_sync(0xffffffffu, amp[j].y, 1 << b);
            ull acc = 0ull;
            ffma2(acc, pack2(amp[j].x, amp[j].x), Ap);
            ffma2(acc, pack2(amp[j].y, amp[j].y), An);
            ffma2(acc, pack2(pr, pr), Bp);
            ffma2(acc, pack2(pi, pi), Bn);
            amp[j] = unpack2(acc);
        }
    }
    #pragma unroll
    for (int q = 5; q < 8; q++) {
        float4 uv = uvL[q];
        int p = 7 - q;
        ull A00p = pack2( uv.x,  uv.y), A00n = pack2(-uv.y,  uv.x);
        ull A01p = pack2(-uv.z,  uv.w), A01n = pack2(-uv.w, -uv.z);
        ull A10p = pack2( uv.z,  uv.w), A10n = pack2(-uv.w,  uv.z);
        ull A11p = pack2( uv.x, -uv.y), A11n = pack2( uv.y,  uv.x);
        #pragma unroll
        for (int t = 0; t < 4; t++) {
            int lowm = (1 << p) - 1;
            int j0 = ((t & ~lowm) << 1) | (t & lowm);
            int j1 = j0 | (1 << p);
            float2 a0 = amp[j0], a1 = amp[j1];
            ull sx0 = pack2(a0.x, a0.x), sy0 = pack2(a0.y, a0.y);
            ull sx1 = pack2(a1.x, a1.x), sy1 = pack2(a1.y, a1.y);
            ull acc0 = 0ull, acc1 = 0ull;
            ffma2(acc0, sx0, A00p); ffma2(acc0, sy0, A00n);
            ffma2(acc0, sx1, A01p); ffma2(acc0, sy1, A01n);
            ffma2(acc1, sx0, A10p); ffma2(acc1, sy0, A10n);
            ffma2(acc1, sx1, A11p); ffma2(acc1, sy1, A11n);
            amp[j0] = unpack2(acc0);
            amp[j1] = unpack2(acc1);
        }
    }
    if (docz) {
        #pragma unroll
        for (int j = 0; j < 8; j++) { amp[j].x *= sgn[j]; amp[j].y *= sgn[j]; }
    }
}

// ---------------- K1: build segment columns + w1 (uniform 100-layer workers) ----------------
// warps    0..1023: segment s = gw>>8 of U2/U3 (100 layers), column gw&255.
// warps 1024..1279: block-1 second-half matrix S_b1s2 (layers 100..199), column gw-1024.
// warp  1280      : w1 = (block-1 layers 0..99) e0.
__global__ void __launch_bounds__(256) k_build() {
    int gw = blockIdx.x * 8 + (threadIdx.x >> 5);
    if (gw >= 1281) return;
    int lane = threadIdx.x & 31;

    int Lbase, col;
    bool czlast;
    float2* outp;
    float initv;
    if (gw < 1024) {
        int s = gw >> 8;
        col = gw & 255;
        Lbase = 200 + s * 100;        // s=0:200, 1:300, 2:400, 3:500
        czlast = (s != 3);            // only U3-seg2's final layer has no CZ
        outp = &g_S[s][col * NS];
        initv = (s == 0 || s == 2) ? czsign(col) : 1.0f;  // fold encode-Dcz into seg1 init
    } else if (gw < 1280) {
        col = gw - 1024;
        Lbase = 100;                  // block-1 layers 100..199 (all carry CZ)
        czlast = true;
        outp = &g_S[4][col * NS];
        initv = 1.0f;
    } else {
        col = 0; Lbase = 0; czlast = true; outp = g_w1; initv = 1.0f;  // layers 0..99
    }

    float2 amp[8];
    float  sgn[8];
    #pragma unroll
    for (int j = 0; j < 8; j++) {
        int n = lane * 8 + j;
        amp[j] = (n == col) ? make_float2(initv, 0.f) : make_float2(0.f, 0.f);
        sgn[j] = czsign(n);
    }

    float4 uvA[8], uvB[8];
    #pragma unroll
    for (int q = 0; q < 8; q++) uvA[q] = g_uv[Lbase * 8 + q];

    for (int l = 0; l < 100; l += 2) {
        #pragma unroll
        for (int q = 0; q < 8; q++) uvB[q] = g_uv[(Lbase + l + 1) * 8 + q];
        seg_step(amp, uvA, sgn, lane, (l < 99) || czlast);
        if (l + 2 < 100) {
            #pragma unroll
            for (int q = 0; q < 8; q++) uvA[q] = g_uv[(Lbase + l + 2) * 8 + q];
        }
        seg_step(amp, uvB, sgn, lane, (l + 1 < 99) || czlast);
    }

    float4* o4 = reinterpret_cast<float4*>(outp);
    #pragma unroll
    for (int jj = 0; jj < 4; jj++)
        o4[lane * 4 + jj] = make_float4(amp[2 * jj].x, amp[2 * jj].y,
                                        amp[2 * jj + 1].x, amp[2 * jj + 1].y);
}

// ---------------- K1b: combine segments ----------------
// blocks 0..15:  U' = S2 * S1 -> g_WT [k][m] complex (as before)
// block  16:     v0 = S_b1s2 * w1  (256x256 complex GEMV)
__global__ void __launch_bounds__(256) k_comb() {
    extern __shared__ float smraw[];
    float2* sPsi = (float2*)smraw;            // NS * NTP
    float2* sA2  = sPsi + NS * NTP;           // 2 x 2048 ping-pong

    int tid = threadIdx.x, lane = tid & 31, warp = tid >> 5;

    if (blockIdx.x == 16) {
        // v0 GEMV: thread m computes v0[m] = sum_c S4[c][m] * w1[c]
        float2* sw = sPsi;                    // reuse first 2KB of dynamic smem
        sw[tid] = g_w1[tid];
        __syncthreads();
        ull acc = 0ull;
        const float2* __restrict__ S4 = g_S[4];
        for (int c = 0; c < NS; c++) {
            float2 s = S4[c * NS + tid];
            float2 w = sw[c];
            ffma2(acc, pack2(s.x, s.y), pack2(w.x, w.x));
            ffma2(acc, pack2(s.y, s.x), pack2(-w.y, w.y));
        }
        g_v0[tid] = unpack2(acc);
        return;
    }

    int g = blockIdx.x >> 3;
    int cbase = (blockIdx.x & 7) * 32;
    const float2* __restrict__ S1 = g_S[2 * g];
    const float2* __restrict__ AT = g_S[2 * g + 1];   // AT[k*256+m] = S2[m][k]
    float2* W = g_WT[g];

    for (int idx = tid; idx < NS * NT; idx += 256) {
        int k = idx & 255, b = idx >> 8;
        sPsi[k * NTP + b] = S1[(cbase + b) * NS + k];
    }
    float2 pre[8];
    #pragma unroll
    for (int r = 0; r < 8; r++) pre[r] = AT[tid + r * 256];
    __syncthreads();

    int mh = warp >> 2, bo = warp & 3;
    int mbase = mh * 128 + lane * 4;
    ull acc[4][8];
    #pragma unroll
    for (int r = 0; r < 4; r++)
        #pragma unroll
        for (int j = 0; j < 8; j++) acc[r][j] = 0ull;

    for (int kc = 0; kc < 32; kc++) {
        float2* buf = sA2 + (kc & 1) * 2048;
        #pragma unroll
        for (int r = 0; r < 8; r++) buf[tid + r * 256] = pre[r];
        if (kc + 1 < 32) {
            #pragma unroll
            for (int r = 0; r < 8; r++) pre[r] = AT[(kc + 1) * 2048 + tid + r * 256];
        }
        __syncthreads();
        #pragma unroll
        for (int kk = 0; kk < 8; kk++) {
            int k = kc * 8 + kk;
            float4 a01 = *reinterpret_cast<const float4*>(&buf[kk * 256 + mbase]);
            float4 a23 = *reinterpret_cast<const float4*>(&buf[kk * 256 + mbase + 2]);
            ull ap[4], as_[4];
            ap[0] = pack2(a01.x, a01.y); as_[0] = pack2(a01.y, a01.x);
            ap[1] = pack2(a01.z, a01.w); as_[1] = pack2(a01.w, a01.z);
            ap[2] = pack2(a23.x, a23.y); as_[2] = pack2(a23.y, a23.x);
            ap[3] = pack2(a23.z, a23.w); as_[3] = pack2(a23.w, a23.z);
            #pragma unroll
            for (int j = 0; j < 8; j++) {
                float2 bv = sPsi[k * NTP + bo * 8 + j];
                ull Br = pack2(bv.x, bv.x);
                ull Bn = pack2(-bv.y, bv.y);
                #pragma unroll
                for (int r = 0; r < 4; r++) {
                    ffma2(acc[r][j], ap[r], Br);
                    ffma2(acc[r][j], as_[r], Bn);
                }
            }
        }
        __syncthreads();
    }
    #pragma unroll
    for (int j = 0; j < 8; j++) {
        int c = cbase + bo * 8 + j;
        float2 e0 = unpack2(acc[0][j]), e1 = unpack2(acc[1][j]);
        float2 e2 = unpack2(acc[2][j]), e3 = unpack2(acc[3][j]);
        *reinterpret_cast<float4*>(&W[c * NS + mbase])     = make_float4(e0.x, e0.y, e1.x, e1.y);
        *reinterpret_cast<float4*>(&W[c * NS + mbase + 2]) = make_float4(e2.x, e2.y, e3.x, e3.y);
    }
}

// ---------------- K2: fused per-batch pipeline (exact R8 version) ----------------
__device__ __forceinline__ void su2_mul(float& Eur, float& Eui, float& Evr, float& Evi,
                                        float gur, float gui, float gvr, float gvi) {
    float ur = gur * Eur - gui * Eui - (gvr * Evr + gvi * Evi);
    float ui = gur * Eui + gui * Eur - (gvr * Evi - gvi * Evr);
    float vr = gvr * Eur - gvi * Eui + (gur * Evr + gui * Evi);
    float vi = gvr * Eui + gvi * Eur + (gur * Evi - gui * Evr);
    Eur = ur; Eui = ui; Evr = vr; Evi = vi;
}

__device__ __forceinline__ float4 compose_E(const float* __restrict__ x, int bg,
                                            int xoff, int enc, int i) {
    float Eur = 1.f, Eui = 0.f, Evr = 0.f, Evi = 0.f;
    #pragma unroll
    for (int j = 0; j < 4; j++) {
        float2 p0 = g_encphi[enc * 64 + 8 * i + 2 * j];
        float2 p1 = g_encphi[enc * 64 + 8 * i + 2 * j + 1];
        float xv = x[(size_t)bg * NXF + xoff + 4 * i + j];
        float sx, cx;
        sincosf(0.5f * xv, &sx, &cx);
        if ((j & 1) == 0) {
            su2_mul(Eur, Eui, Evr, Evi, p0.x, 0.f, p0.y, 0.f);   // RY(p0)
            su2_mul(Eur, Eui, Evr, Evi, cx, 0.f, 0.f, -sx);      // RX(x)
            su2_mul(Eur, Eui, Evr, Evi, p1.x, 0.f, p1.y, 0.f);   // RY(p1)
        } else {
            su2_mul(Eur, Eui, Evr, Evi, p0.x, 0.f, 0.f, -p0.y);  // RX(p0)
            su2_mul(Eur, Eui, Evr, Evi, cx, 0.f, sx, 0.f);       // RY(x)
            su2_mul(Eur, Eui, Evr, Evi, p1.x, 0.f, 0.f, -p1.y);  // RX(p1)
        }
    }
    return make_float4(Eur, Eui, Evr, Evi);
}

__device__ __forceinline__ void apply_gates(float2* sPsi, const float4* sE, int tid) {
    #pragma unroll
    for (int q = 0; q < 8; q++) {
        int p = 7 - q;
        int low = (1 << p) - 1;
        #pragma unroll
        for (int it = 0; it < (128 * NT) / 256; it++) {  // 16
            int task = tid + it * 256;
            int b = task & (NT - 1);
            int pr = task >> 5;
            int n0 = ((pr & ~low) << 1) | (pr & low);
            int n1 = n0 | (1 << p);
            float4 E = sE[q * NT + b];
            float2 a0 = sPsi[n0 * NTP + b];
            float2 a1 = sPsi[n1 * NTP + b];
            float2 b0, b1;
            b0.x = E.x * a0.x - E.y * a0.y - (E.z * a1.x + E.w * a1.y);
            b0.y = E.x * a0.y + E.y * a0.x - (E.z * a1.y - E.w * a1.x);
            b1.x = E.z * a0.x - E.w * a0.y + (E.x * a1.x + E.y * a1.y);
            b1.y = E.z * a0.y + E.w * a0.x + (E.x * a1.y - E.y * a1.x);
            sPsi[n0 * NTP + b] = b0;
            sPsi[n1 * NTP + b] = b1;
        }
        __syncthreads();
    }
}

// in-place complex GEMM, packed f32x2 FMAs, ping-pong A staging (R5/R8 version):
//   sPsi[m][b] = sum_k AT[k][m] * sPsi[k][b]
__device__ __forceinline__ void do_gemm(float2* sPsi, float2* sA2,
                                        const float2* __restrict__ AT,
                                        float2 pre[8],
                                        int tid, int lane, int warp) {
    int mh = warp >> 2;            // m-half:   m = mh*128 + lane*4 + rr
    int bo = warp & 3;             // b-octet:  b = bo*8 + j
    int mbase = mh * 128 + lane * 4;
    ull acc[4][8];
    #pragma unroll
    for (int r = 0; r < 4; r++)
        #pragma unroll
        for (int j = 0; j < 8; j++) acc[r][j] = 0ull;

    for (int kc = 0; kc < 32; kc++) {
        float2* buf = sA2 + (kc & 1) * 2048;
        #pragma unroll
        for (int r = 0; r < 8; r++) buf[tid + r * 256] = pre[r];
        if (kc + 1 < 32) {
            #pragma unroll
            for (int r = 0; r < 8; r++) pre[r] = AT[(kc + 1) * 2048 + tid + r * 256];
        }
        __syncthreads();
        #pragma unroll
        for (int kk = 0; kk < 8; kk++) {
            int k = kc * 8 + kk;
            float4 a01 = *reinterpret_cast<const float4*>(&buf[kk * 256 + mbase]);
            float4 a23 = *reinterpret_cast<const float4*>(&buf[kk * 256 + mbase + 2]);
            ull ap[4], as_[4];
            ap[0] = pack2(a01.x, a01.y); as_[0] = pack2(a01.y, a01.x);
            ap[1] = pack2(a01.z, a01.w); as_[1] = pack2(a01.w, a01.z);
            ap[2] = pack2(a23.x, a23.y); as_[2] = pack2(a23.y, a23.x);
            ap[3] = pack2(a23.z, a23.w); as_[3] = pack2(a23.w, a23.z);
            #pragma unroll
            for (int j = 0; j < 8; j++) {
                float2 bv = sPsi[k * NTP + bo * 8 + j];
                ull Br = pack2(bv.x, bv.x);
                ull Bn = pack2(-bv.y, bv.y);
                #pragma unroll
                for (int r = 0; r < 4; r++) {
                    ffma2(acc[r][j], ap[r], Br);    // (a.r, a.i) * (b.r, b.r)
                    ffma2(acc[r][j], as_[r], Bn);   // (a.i, a.r) * (-b.i, b.i)
                }
            }
        }
    }
    __syncthreads();  // all reads of sPsi done before overwrite
    #pragma unroll
    for (int r = 0; r < 4; r++)
        #pragma unroll
        for (int j = 0; j < 8; j++)
            *reinterpret_cast<ull*>(&sPsi[(mbase + r) * NTP + bo * 8 + j]) = acc[r][j];
    __syncthreads();
}

__global__ void __launch_bounds__(256, 2) k_main(const float* __restrict__ x,
                                                 float* __restrict__ out) {
    extern __shared__ float smraw[];
    float2* sPsi = (float2*)smraw;              // NS * NTP           (67584 B)
    float2* sA2  = sPsi + NS * NTP;             // 2 x 2048 float2    (32768 B)
    float4* sE   = (float4*)(sA2 + 2 * 2048);   // 8 * NT float4      ( 4096 B)

    int tid = threadIdx.x;
    int lane = tid & 31, warp = tid >> 5;       // 8 warps
    int bbase = blockIdx.x * NT;

    // ---- prefetch first A-chunk of U2' (hidden behind encode compute) ----
    float2 pre[8];
    #pragma unroll
    for (int r = 0; r < 8; r++) pre[r] = g_WT[0][tid + r * 256];

    // ---- E1 compose: tid -> (b = tid&31, i = tid>>5) ----
    {
        int b = tid & (NT - 1), i = tid >> 5;
        sE[i * NT + b] = compose_E(x, bbase + b, 0, 0, i);
    }
    // ---- init Psi = v0 (broadcast over batches) ----
    for (int idx = tid; idx < NS * NT; idx += 256) {
        int b = idx & (NT - 1), amp = idx >> 5;
        sPsi[amp * NTP + b] = g_v0[amp];
    }
    __syncthreads();

    apply_gates(sPsi, sE, tid);                 // encode 1 (CZ folded into U2')
    do_gemm(sPsi, sA2, g_WT[0], pre, tid, lane, warp);

    // ---- prefetch first A-chunk of U3', then E2 compose ----
    #pragma unroll
    for (int r = 0; r < 8; r++) pre[r] = g_WT[1][tid + r * 256];
    {
        int b = tid & (NT - 1), i = tid >> 5;
        sE[i * NT + b] = compose_E(x, bbase + b, 32, 1, i);
    }
    __syncthreads();

    apply_gates(sPsi, sE, tid);                 // encode 2 (CZ folded into U3')
    do_gemm(sPsi, sA2, g_WT[1], pre, tid, lane, warp);

    // ---- measurement: warp w handles batches w*4..w*4+3 ----
    for (int j = 0; j < 4; j++) {
        int b = warp * 4 + j;
        float sums[8];
        #pragma unroll
        for (int k = 0; k < 8; k++) sums[k] = 0.f;
        #pragma unroll
        for (int r = 0; r < 8; r++) {
            int m = lane + 32 * r;
            float2 ps = sPsi[m * NTP + b];
            float p2 = ps.x * ps.x + ps.y * ps.y;
            sums[4] += (m & 128) ? -p2 : p2;   // Z q0
            sums[5] += (m & 64)  ? -p2 : p2;   // Z q1
            sums[6] += (m & 32)  ? -p2 : p2;   // Z q2
            sums[7] += (m & 16)  ? -p2 : p2;   // Z q3
            float2 q0 = sPsi[(m ^ 128) * NTP + b];
            sums[0] += ps.x * q0.x + ps.y * q0.y;   // X q0
            float2 q1 = sPsi[(m ^ 64) * NTP + b];
            sums[1] += ps.x * q1.x + ps.y * q1.y;   // X q1
            float2 q2 = sPsi[(m ^ 32) * NTP + b];
            sums[2] += ps.x * q2.x + ps.y * q2.y;   // X q2
            float2 q3 = sPsi[(m ^ 16) * NTP + b];
            sums[3] += ps.x * q3.x + ps.y * q3.y;   // X q3
        }
        #pragma unroll
        for (int off = 16; off; off >>= 1) {
            #pragma unroll
            for (int k = 0; k < 8; k++)
                sums[k] += __shfl_xor_sync(0xffffffffu, sums[k], off);
        }
        if (lane < 8) out[(size_t)(bbase + b) * 8 + lane] = sums[lane];
    }
}

// ---------------- launch ----------------
extern "C" void kernel_launch(void* const* d_in, const int* in_sizes, int n_in,
                              void* d_out, int out_size) {
    const float* x   = (const float*)d_in[0];
    const float* phi = (const float*)d_in[1];
    float* out = (float*)d_out;

    const size_t smem_c = (size_t)(NS * NTP) * sizeof(float2)   // 67584
                        + (size_t)(2 * 2048) * sizeof(float2);  // 32768
    const size_t smem_m = (size_t)(NS * NTP) * sizeof(float2)   // 67584
                        + (size_t)(2 * 2048) * sizeof(float2)   // 32768
                        + (size_t)(8 * NT) * sizeof(float4);    //  4096
    cudaFuncSetAttribute(k_comb, cudaFuncAttributeMaxDynamicSharedMemorySize, (int)smem_c);
    cudaFuncSetAttribute(k_main, cudaFuncAttributeMaxDynamicSharedMemorySize, (int)smem_m);

    k_tables<<<20, 256>>>(phi);
    k_build<<<161, 256>>>();
    k_comb<<<17, 256, smem_c>>>();
    k_main<<<NBLK, 256, smem_m>>>(x, out);
}

// round 15
// speedup vs baseline: 1.1303x; 1.1303x over previous
#include <cuda_runtime.h>
#include <math.h>

#define NQ 8
#define NS 256          // 2^8 amplitudes
#define DEPTH 200
#define BSZ 16384
#define NXF 64
#define NT 32           // batches per block in main kernel
#define NTP 33          // padded batch stride in shared
#define NBLK (BSZ/NT)   // 512 blocks

typedef unsigned long long ull;

// ---------------- device globals (no cudaMalloc allowed) ----------------
__device__ float4 g_uv[600 * 8];     // per layer/qubit: (u.re,u.im,v.re,v.im) of RY(b)*RX(a)
__device__ float2 g_encphi[128];     // (cos(phi/2), sin(phi/2)) for encode phi angles
__device__ float2 g_v0[NS];          // U1 |0>
__device__ float2 g_S[4][NS * NS];   // segment columns: [s][c*256+m]; s:0=U2s1,1=U2s2,2=U3s1,3=U3s2
__device__ float2 g_WT[2][NS * NS];  // U'[m][k] stored [k*256+m]  (0=U2', 1=U3')

// ---------------- packed f32x2 helpers ----------------
__device__ __forceinline__ void ffma2(ull& d, ull a, ull b) {
    asm("fma.rn.f32x2 %0, %1, %2, %0;" : "+l"(d) : "l"(a), "l"(b));
}
__device__ __forceinline__ ull pack2(float lo, float hi) {
    ull r; asm("mov.b64 %0, {%1, %2};" : "=l"(r) : "f"(lo), "f"(hi)); return r;
}
__device__ __forceinline__ float2 unpack2(ull v) {
    float2 r; asm("mov.b64 {%0, %1}, %2;" : "=f"(r.x), "=f"(r.y) : "l"(v)); return r;
}

// ring-CZ parity sign for amplitude index n (qubit i <-> bit 7-i)
__device__ __forceinline__ float czsign(int n) {
    int par = __popc(n & (n >> 1)) + ((n & (n >> 7)) & 1);
    return (par & 1) ? -1.0f : 1.0f;
}

// ---------------- K0: angle tables ----------------
__global__ void k_tables(const float* __restrict__ phi) {
    int tid = blockIdx.x * blockDim.x + threadIdx.x;
    int stride = gridDim.x * blockDim.x;
    for (int idx = tid; idx < 600 * 8; idx += stride) {
        int L = idx >> 3, q = idx & 7;
        int base, l;
        if (L < 200)      { base = 0;    l = L; }
        else if (L < 400) { base = 3264; l = L - 200; }
        else              { base = 6528; l = L - 400; }
        float a = phi[base + l * 16 + q];
        float b = phi[base + l * 16 + 8 + q];
        float ca, sa, cb, sb;
        sincosf(0.5f * a, &sa, &ca);
        sincosf(0.5f * b, &sb, &cb);
        g_uv[idx] = make_float4(ca * cb, sa * sb, ca * sb, -sa * cb);
    }
    for (int idx = tid; idx < 128; idx += stride) {
        int base = (idx < 64) ? 3200 : 6400;
        float p = phi[base + idx];
        float c, s;
        sincosf(0.5f * p, &s, &c);
        g_encphi[idx] = make_float2(c, s);
    }
}

// ---------------- segment layer step (register/shuffle state machine) ----------------
__device__ __forceinline__ void seg_step(float2 amp[8], const float4 uvL[8],
                                         const float sgn[8], int lane, bool docz) {
    #pragma unroll
    for (int q = 0; q < 5; q++) {
        float4 uv = uvL[q];
        int b = 4 - q;
        int mybit = (lane >> b) & 1;
        float mai = mybit ? -uv.y : uv.y;
        float mbr = mybit ?  uv.z : -uv.z;
        ull Ap = pack2(uv.x, mai),  An = pack2(-mai, uv.x);
        ull Bp = pack2(mbr, uv.w),  Bn = pack2(-uv.w, mbr);
        #pragma unroll
        for (int j = 0; j < 8; j++) {
            float pr = __shfl_xor_sync(0xffffffffu, amp[j].x, 1 << b);
            float pi = __shfl_xor_sync(0xffffffffu, amp[j].y, 1 << b);
            ull acc = 0ull;
            ffma2(acc, pack2(amp[j].x, amp[j].x), Ap);
            ffma2(acc, pack2(amp[j].y, amp[j].y), An);
            ffma2(acc, pack2(pr, pr), Bp);
            ffma2(acc, pack2(pi, pi), Bn);
            amp[j] = unpack2(acc);
        }
    }
    #pragma unroll
    for (int q = 5; q < 8; q++) {
        float4 uv = uvL[q];
        int p = 7 - q;
        ull A00p = pack2( uv.x,  uv.y), A00n = pack2(-uv.y,  uv.x);
        ull A01p = pack2(-uv.z,  uv.w), A01n = pack2(-uv.w, -uv.z);
        ull A10p = pack2( uv.z,  uv.w), A10n = pack2(-uv.w,  uv.z);
        ull A11p = pack2( uv.x, -uv.y), A11n = pack2( uv.y,  uv.x);
        #pragma unroll
        for (int t = 0; t < 4; t++) {
            int lowm = (1 << p) - 1;
            int j0 = ((t & ~lowm) << 1) | (t & lowm);
            int j1 = j0 | (1 << p);
            float2 a0 = amp[j0], a1 = amp[j1];
            ull sx0 = pack2(a0.x, a0.x), sy0 = pack2(a0.y, a0.y);
            ull sx1 = pack2(a1.x, a1.x), sy1 = pack2(a1.y, a1.y);
            ull acc0 = 0ull, acc1 = 0ull;
            ffma2(acc0, sx0, A00p); ffma2(acc0, sy0, A00n);
            ffma2(acc0, sx1, A01p); ffma2(acc0, sy1, A01n);
            ffma2(acc1, sx0, A10p); ffma2(acc1, sy0, A10n);
            ffma2(acc1, sx1, A11p); ffma2(acc1, sy1, A11n);
            amp[j0] = unpack2(acc0);
            amp[j1] = unpack2(acc1);
        }
    }
    if (docz) {
        #pragma unroll
        for (int j = 0; j < 8; j++) { amp[j].x *= sgn[j]; amp[j].y *= sgn[j]; }
    }
}

// ---------------- K1: build segment columns + v0 (exact R8 layout) ----------------
// warps 0..1023: segment s = gw>>8 (100 layers each), column gw&255.
// warp 1024: v0 over full 200 layers of block 1.
__global__ void __launch_bounds__(256) k_build() {
    int gw = blockIdx.x * 8 + (threadIdx.x >> 5);
    if (gw >= 1025) return;
    int lane = threadIdx.x & 31;

    int Lbase, NL, col;
    bool czlast;
    float2* outp;
    float initv;
    if (gw < 1024) {
        int s = gw >> 8;
        col = gw & 255;
        Lbase = 200 + s * 100;        // s=0:200, 1:300, 2:400, 3:500
        NL = 100;
        czlast = (s != 3);            // only U3-seg2's final layer has no CZ
        outp = &g_S[s][col * NS];
        initv = (s == 0 || s == 2) ? czsign(col) : 1.0f;  // fold encode-Dcz into seg1 init
    } else {
        Lbase = 0; NL = DEPTH; czlast = true; col = 0; outp = g_v0; initv = 1.0f;
    }

    float2 amp[8];
    float  sgn[8];
    #pragma unroll
    for (int j = 0; j < 8; j++) {
        int n = lane * 8 + j;
        amp[j] = (n == col) ? make_float2(initv, 0.f) : make_float2(0.f, 0.f);
        sgn[j] = czsign(n);
    }

    float4 uvA[8], uvB[8];
    #pragma unroll
    for (int q = 0; q < 8; q++) uvA[q] = g_uv[Lbase * 8 + q];

    for (int l = 0; l < NL; l += 2) {
        #pragma unroll
        for (int q = 0; q < 8; q++) uvB[q] = g_uv[(Lbase + l + 1) * 8 + q];
        seg_step(amp, uvA, sgn, lane, (l < NL - 1) || czlast);
        if (l + 2 < NL) {
            #pragma unroll
            for (int q = 0; q < 8; q++) uvA[q] = g_uv[(Lbase + l + 2) * 8 + q];
        }
        seg_step(amp, uvB, sgn, lane, (l + 1 < NL - 1) || czlast);
    }

    float4* o4 = reinterpret_cast<float4*>(outp);
    #pragma unroll
    for (int jj = 0; jj < 4; jj++)
        o4[lane * 4 + jj] = make_float4(amp[2 * jj].x, amp[2 * jj].y,
                                        amp[2 * jj + 1].x, amp[2 * jj + 1].y);
}

// ---------------- K1b: combine segments  U' = S2 * S1 -> g_WT [k][m] complex ----------------
__global__ void __launch_bounds__(256) k_comb() {
    extern __shared__ float smraw[];
    float2* sPsi = (float2*)smraw;            // NS * NTP
    float2* sA2  = sPsi + NS * NTP;           // 2 x 2048 ping-pong

    int tid = threadIdx.x, lane = tid & 31, warp = tid >> 5;
    int g = blockIdx.x >> 3;
    int cbase = (blockIdx.x & 7) * 32;
    const float2* __restrict__ S1 = g_S[2 * g];
    const float2* __restrict__ AT = g_S[2 * g + 1];   // AT[k*256+m] = S2[m][k]
    float2* W = g_WT[g];

    for (int idx = tid; idx < NS * NT; idx += 256) {
        int k = idx & 255, b = idx >> 8;
        sPsi[k * NTP + b] = S1[(cbase + b) * NS + k];
    }
    float2 pre[8];
    #pragma unroll
    for (int r = 0; r < 8; r++) pre[r] = AT[tid + r * 256];
    __syncthreads();

    int mh = warp >> 2, bo = warp & 3;
    int mbase = mh * 128 + lane * 4;
    ull acc[4][8];
    #pragma unroll
    for (int r = 0; r < 4; r++)
        #pragma unroll
        for (int j = 0; j < 8; j++) acc[r][j] = 0ull;

    for (int kc = 0; kc < 32; kc++) {
        float2* buf = sA2 + (kc & 1) * 2048;
        #pragma unroll
        for (int r = 0; r < 8; r++) buf[tid + r * 256] = pre[r];
        if (kc + 1 < 32) {
            #pragma unroll
            for (int r = 0; r < 8; r++) pre[r] = AT[(kc + 1) * 2048 + tid + r * 256];
        }
        __syncthreads();
        #pragma unroll
        for (int kk = 0; kk < 8; kk++) {
            int k = kc * 8 + kk;
            float4 a01 = *reinterpret_cast<const float4*>(&buf[kk * 256 + mbase]);
            float4 a23 = *reinterpret_cast<const float4*>(&buf[kk * 256 + mbase + 2]);
            ull ap[4], as_[4];
            ap[0] = pack2(a01.x, a01.y); as_[0] = pack2(a01.y, a01.x);
            ap[1] = pack2(a01.z, a01.w); as_[1] = pack2(a01.w, a01.z);
            ap[2] = pack2(a23.x, a23.y); as_[2] = pack2(a23.y, a23.x);
            ap[3] = pack2(a23.z, a23.w); as_[3] = pack2(a23.w, a23.z);
            #pragma unroll
            for (int j = 0; j < 8; j++) {
                float2 bv = sPsi[k * NTP + bo * 8 + j];
                ull Br = pack2(bv.x, bv.x);
                ull Bn = pack2(-bv.y, bv.y);
                #pragma unroll
                for (int r = 0; r < 4; r++) {
                    ffma2(acc[r][j], ap[r], Br);
                    ffma2(acc[r][j], as_[r], Bn);
                }
            }
        }
        __syncthreads();
    }
    #pragma unroll
    for (int j = 0; j < 8; j++) {
        int c = cbase + bo * 8 + j;
        float2 e0 = unpack2(acc[0][j]), e1 = unpack2(acc[1][j]);
        float2 e2 = unpack2(acc[2][j]), e3 = unpack2(acc[3][j]);
        *reinterpret_cast<float4*>(&W[c * NS + mbase])     = make_float4(e0.x, e0.y, e1.x, e1.y);
        *reinterpret_cast<float4*>(&W[c * NS + mbase + 2]) = make_float4(e2.x, e2.y, e3.x, e3.y);
    }
}

// ---------------- K2: fused per-batch pipeline ----------------
__device__ __forceinline__ void su2_mul(float& Eur, float& Eui, float& Evr, float& Evi,
                                        float gur, float gui, float gvr, float gvi) {
    float ur = gur * Eur - gui * Eui - (gvr * Evr + gvi * Evi);
    float ui = gur * Eui + gui * Eur - (gvr * Evi - gvi * Evr);
    float vr = gvr * Eur - gvi * Eui + (gur * Evr + gui * Evi);
    float vi = gvr * Eui + gvi * Eur + (gur * Evi - gui * Evr);
    Eur = ur; Eui = ui; Evr = vr; Evi = vi;
}

__device__ __forceinline__ float4 compose_E(const float* __restrict__ x, int bg,
                                            int xoff, int enc, int i) {
    float Eur = 1.f, Eui = 0.f, Evr = 0.f, Evi = 0.f;
    #pragma unroll
    for (int j = 0; j < 4; j++) {
        float2 p0 = g_encphi[enc * 64 + 8 * i + 2 * j];
        float2 p1 = g_encphi[enc * 64 + 8 * i + 2 * j + 1];
        float xv = x[(size_t)bg * NXF + xoff + 4 * i + j];
        float sx, cx;
        sincosf(0.5f * xv, &sx, &cx);
        if ((j & 1) == 0) {
            su2_mul(Eur, Eui, Evr, Evi, p0.x, 0.f, p0.y, 0.f);   // RY(p0)
            su2_mul(Eur, Eui, Evr, Evi, cx, 0.f, 0.f, -sx);      // RX(x)
            su2_mul(Eur, Eui, Evr, Evi, p1.x, 0.f, p1.y, 0.f);   // RY(p1)
        } else {
            su2_mul(Eur, Eui, Evr, Evi, p0.x, 0.f, 0.f, -p0.y);  // RX(p0)
            su2_mul(Eur, Eui, Evr, Evi, cx, 0.f, sx, 0.f);       // RY(x)
            su2_mul(Eur, Eui, Evr, Evi, p1.x, 0.f, 0.f, -p1.y);  // RX(p1)
        }
    }
    return make_float4(Eur, Eui, Evr, Evi);
}

// compose encode E for this thread's (q = tid>>5, b = tid&31) and write the
// 8 packed FFMA2 operand slots into sEp[(q*8+s)*32 + b].
__device__ __forceinline__ void compose_pack(const float* __restrict__ x, int bbase,
                                             int xoff, int enc, ull* sEp, int tid) {
    int b = tid & 31, q = tid >> 5;
    float4 E = compose_E(x, bbase + b, xoff, enc, q);
    ull* dst = sEp + q * 8 * 32 + b;
    dst[0 * 32] = pack2( E.x,  E.y);   // x a0.x -> b0
    dst[1 * 32] = pack2(-E.y,  E.x);   // x a0.y -> b0
    dst[2 * 32] = pack2(-E.z,  E.w);   // x a1.x -> b0
    dst[3 * 32] = pack2(-E.w, -E.z);   // x a1.y -> b0
    dst[4 * 32] = pack2( E.z,  E.w);   // x a0.x -> b1
    dst[5 * 32] = pack2(-E.w,  E.z);   // x a0.y -> b1
    dst[6 * 32] = pack2( E.x, -E.y);   // x a1.x -> b1
    dst[7 * 32] = pack2( E.y,  E.x);   // x a1.y -> b1
}

// packed-FFMA2 gate application: 8 passes, gate operands hoisted per pass.
__device__ __forceinline__ void apply_gates_p(float2* sPsi, const ull* sEp, int tid) {
    int b = tid & 31;
    #pragma unroll
    for (int q = 0; q < 8; q++) {
        ull G0 = sEp[(q * 8 + 0) * 32 + b];
        ull G1 = sEp[(q * 8 + 1) * 32 + b];
        ull G2 = sEp[(q * 8 + 2) * 32 + b];
        ull G3 = sEp[(q * 8 + 3) * 32 + b];
        ull G4 = sEp[(q * 8 + 4) * 32 + b];
        ull G5 = sEp[(q * 8 + 5) * 32 + b];
        ull G6 = sEp[(q * 8 + 6) * 32 + b];
        ull G7 = sEp[(q * 8 + 7) * 32 + b];
        int p = 7 - q;
        int low = (1 << p) - 1;
        #pragma unroll
        for (int it = 0; it < 16; it++) {
            int pr = (tid >> 5) + it * 8;
            int n0 = ((pr & ~low) << 1) | (pr & low);
            int n1 = n0 | (1 << p);
            float2 a0 = sPsi[n0 * NTP + b];
            float2 a1 = sPsi[n1 * NTP + b];
            ull x0 = pack2(a0.x, a0.x), y0 = pack2(a0.y, a0.y);
            ull x1 = pack2(a1.x, a1.x), y1 = pack2(a1.y, a1.y);
            ull acc0 = 0ull, acc1 = 0ull;
            ffma2(acc0, x0, G0); ffma2(acc0, y0, G1);
            ffma2(acc0, x1, G2); ffma2(acc0, y1, G3);
            ffma2(acc1, x0, G4); ffma2(acc1, y0, G5);
            ffma2(acc1, x1, G6); ffma2(acc1, y1, G7);
            *reinterpret_cast<ull*>(&sPsi[n0 * NTP + b]) = acc0;
            *reinterpret_cast<ull*>(&sPsi[n1 * NTP + b]) = acc1;
        }
        __syncthreads();
    }
}

// in-place complex GEMM, packed f32x2 FMAs, single-buffer A staging (R4 pattern):
//   sPsi[m][b] = sum_k AT[k][m] * sPsi[k][b]
__device__ __forceinline__ void do_gemm(float2* sPsi, float2* sA2,
                                        const float2* __restrict__ AT,
                                        float2 pre[8],
                                        int tid, int lane, int warp) {
    int mh = warp >> 2;            // m-half:   m = mh*128 + lane*4 + rr
    int bo = warp & 3;             // b-octet:  b = bo*8 + j
    int mbase = mh * 128 + lane * 4;
    ull acc[4][8];
    #pragma unroll
    for (int r = 0; r < 4; r++)
        #pragma unroll
        for (int j = 0; j < 8; j++) acc[r][j] = 0ull;

    for (int kc = 0; kc < 32; kc++) {
        __syncthreads();  // previous compute done reading sA2
        #pragma unroll
        for (int r = 0; r < 8; r++) sA2[tid + r * 256] = pre[r];
        __syncthreads();
        if (kc + 1 < 32) {
            #pragma unroll
            for (int r = 0; r < 8; r++) pre[r] = AT[(kc + 1) * 2048 + tid + r * 256];
        }
        #pragma unroll
        for (int kk = 0; kk < 8; kk++) {
            int k = kc * 8 + kk;
            float4 a01 = *reinterpret_cast<const float4*>(&sA2[kk * 256 + mbase]);
            float4 a23 = *reinterpret_cast<const float4*>(&sA2[kk * 256 + mbase + 2]);
            ull ap[4], as_[4];
            ap[0] = pack2(a01.x, a01.y); as_[0] = pack2(a01.y, a01.x);
            ap[1] = pack2(a01.z, a01.w); as_[1] = pack2(a01.w, a01.z);
            ap[2] = pack2(a23.x, a23.y); as_[2] = pack2(a23.y, a23.x);
            ap[3] = pack2(a23.z, a23.w); as_[3] = pack2(a23.w, a23.z);
            #pragma unroll
            for (int j = 0; j < 8; j++) {
                float2 bv = sPsi[k * NTP + bo * 8 + j];
                ull Br = pack2(bv.x, bv.x);
                ull Bn = pack2(-bv.y, bv.y);
                #pragma unroll
                for (int r = 0; r < 4; r++) {
                    ffma2(acc[r][j], ap[r], Br);    // (a.r, a.i) * (b.r, b.r)
                    ffma2(acc[r][j], as_[r], Bn);   // (a.i, a.r) * (-b.i, b.i)
                }
            }
        }
    }
    __syncthreads();  // all reads of sPsi done before overwrite
    #pragma unroll
    for (int r = 0; r < 4; r++)
        #pragma unroll
        for (int j = 0; j < 8; j++)
            *reinterpret_cast<ull*>(&sPsi[(mbase + r) * NTP + bo * 8 + j]) = acc[r][j];
    __syncthreads();
}

__global__ void __launch_bounds__(256, 2) k_main(const float* __restrict__ x,
                                                 float* __restrict__ out) {
    extern __shared__ float smraw[];
    float2* sPsi = (float2*)smraw;              // NS * NTP float2    (67584 B)
    float2* sA2  = sPsi + NS * NTP;             // 2048 float2        (16384 B)
    ull*    sEp  = (ull*)(sA2 + 2048);          // 8*8*32 ull         (16384 B)

    int tid = threadIdx.x;
    int lane = tid & 31, warp = tid >> 5;       // 8 warps
    int bbase = blockIdx.x * NT;

    // ---- prefetch first A-chunk of U2' (hidden behind encode compute) ----
    float2 pre[8];
    #pragma unroll
    for (int r = 0; r < 8; r++) pre[r] = g_WT[0][tid + r * 256];

    // ---- E1 compose + pack ----
    compose_pack(x, bbase, 0, 0, sEp, tid);

    // ---- init Psi = v0 (broadcast over batches) ----
    for (int idx = tid; idx < NS * NT; idx += 256) {
        int b = idx & (NT - 1), amp = idx >> 5;
        sPsi[amp * NTP + b] = g_v0[amp];
    }
    __syncthreads();

    apply_gates_p(sPsi, sEp, tid);              // encode 1 (CZ folded into U2')
    do_gemm(sPsi, sA2, g_WT[0], pre, tid, lane, warp);

    // ---- prefetch first A-chunk of U3', then E2 compose + pack ----
    #pragma unroll
    for (int r = 0; r < 8; r++) pre[r] = g_WT[1][tid + r * 256];
    compose_pack(x, bbase, 32, 1, sEp, tid);
    __syncthreads();

    apply_gates_p(sPsi, sEp, tid);              // encode 2 (CZ folded into U3')
    do_gemm(sPsi, sA2, g_WT[1], pre, tid, lane, warp);

    // ---- measurement: warp w handles batches w*4..w*4+3 ----
    for (int j = 0; j < 4; j++) {
        int b = warp * 4 + j;
        float sums[8];
        #pragma unroll
        for (int k = 0; k < 8; k++) sums[k] = 0.f;
        #pragma unroll
        for (int r = 0; r < 8; r++) {
            int m = lane + 32 * r;
            float2 ps = sPsi[m * NTP + b];
            float p2 = ps.x * ps.x + ps.y * ps.y;
            sums[4] += (m & 128) ? -p2 : p2;   // Z q0
            sums[5] += (m & 64)  ? -p2 : p2;   // Z q1
            sums[6] += (m & 32)  ? -p2 : p2;   // Z q2
            sums[7] += (m & 16)  ? -p2 : p2;   // Z q3
            float2 q0 = sPsi[(m ^ 128) * NTP + b];
            sums[0] += ps.x * q0.x + ps.y * q0.y;   // X q0
            float2 q1 = sPsi[(m ^ 64) * NTP + b];
            sums[1] += ps.x * q1.x + ps.y * q1.y;   // X q1
            float2 q2 = sPsi[(m ^ 32) * NTP + b];
            sums[2] += ps.x * q2.x + ps.y * q2.y;   // X q2
            float2 q3 = sPsi[(m ^ 16) * NTP + b];
            sums[3] += ps.x * q3.x + ps.y * q3.y;   // X q3
        }
        #pragma unroll
        for (int off = 16; off; off >>= 1) {
            #pragma unroll
            for (int k = 0; k < 8; k++)
                sums[k] += __shfl_xor_sync(0xffffffffu, sums[k], off);
        }
        if (lane < 8) out[(size_t)(bbase + b) * 8 + lane] = sums[lane];
    }
}

// ---------------- launch ----------------
extern "C" void kernel_launch(void* const* d_in, const int* in_sizes, int n_in,
                              void* d_out, int out_size) {
    const float* x   = (const float*)d_in[0];
    const float* phi = (const float*)d_in[1];
    float* out = (float*)d_out;

    const size_t smem_c = (size_t)(NS * NTP) * sizeof(float2)   // 67584
                        + (size_t)(2 * 2048) * sizeof(float2);  // 32768
    const size_t smem_m = (size_t)(NS * NTP) * sizeof(float2)   // 67584
                        + (size_t)2048 * sizeof(float2)         // 16384
                        + (size_t)2048 * sizeof(ull);           // 16384
    cudaFuncSetAttribute(k_comb, cudaFuncAttributeMaxDynamicSharedMemorySize, (int)smem_c);
    cudaFuncSetAttribute(k_main, cudaFuncAttributeMaxDynamicSharedMemorySize, (int)smem_m);

    k_tables<<<20, 256>>>(phi);
    k_build<<<129, 256>>>();
    k_comb<<<16, 256, smem_c>>>();
    k_main<<<NBLK, 256, smem_m>>>(x, out);
}

// round 16
// speedup vs baseline: 1.1313x; 1.0009x over previous
#include <cuda_runtime.h>
#include <math.h>

#define NQ 8
#define NS 256          // 2^8 amplitudes
#define DEPTH 200
#define BSZ 16384
#define NXF 64
#define NT 32           // batches per block in main kernel
#define NTP 33          // padded batch stride in shared
#define NBLK (BSZ/NT)   // 512 blocks

typedef unsigned long long ull;

// ---------------- device globals (no cudaMalloc allowed) ----------------
__device__ float4 g_uv[600 * 8];     // per layer/qubit: (u.re,u.im,v.re,v.im) of RY(b)*RX(a)
__device__ float2 g_encphi[128];     // (cos(phi/2), sin(phi/2)) for encode phi angles
__device__ float2 g_v0[NS];          // U1 |0>
__device__ float2 g_S[4][NS * NS];   // segment columns: [s][c*256+m]; s:0=U2s1,1=U2s2,2=U3s1,3=U3s2
__device__ float2 g_WT[2][NS * NS];  // U'[m][k] stored [k*256+m]  (0=U2', 1=U3')

// ---------------- packed f32x2 helpers ----------------
__device__ __forceinline__ void ffma2(ull& d, ull a, ull b) {
    asm("fma.rn.f32x2 %0, %1, %2, %0;" : "+l"(d) : "l"(a), "l"(b));
}
__device__ __forceinline__ ull pack2(float lo, float hi) {
    ull r; asm("mov.b64 %0, {%1, %2};" : "=l"(r) : "f"(lo), "f"(hi)); return r;
}
__device__ __forceinline__ float2 unpack2(ull v) {
    float2 r; asm("mov.b64 {%0, %1}, %2;" : "=f"(r.x), "=f"(r.y) : "l"(v)); return r;
}

// ring-CZ parity sign for amplitude index n (qubit i <-> bit 7-i)
__device__ __forceinline__ float czsign(int n) {
    int par = __popc(n & (n >> 1)) + ((n & (n >> 7)) & 1);
    return (par & 1) ? -1.0f : 1.0f;
}

// ---------------- K0: angle tables ----------------
__global__ void k_tables(const float* __restrict__ phi) {
    int tid = blockIdx.x * blockDim.x + threadIdx.x;
    int stride = gridDim.x * blockDim.x;
    for (int idx = tid; idx < 600 * 8; idx += stride) {
        int L = idx >> 3, q = idx & 7;
        int base, l;
        if (L < 200)      { base = 0;    l = L; }
        else if (L < 400) { base = 3264; l = L - 200; }
        else              { base = 6528; l = L - 400; }
        float a = phi[base + l * 16 + q];
        float b = phi[base + l * 16 + 8 + q];
        float ca, sa, cb, sb;
        sincosf(0.5f * a, &sa, &ca);
        sincosf(0.5f * b, &sb, &cb);
        g_uv[idx] = make_float4(ca * cb, sa * sb, ca * sb, -sa * cb);
    }
    for (int idx = tid; idx < 128; idx += stride) {
        int base = (idx < 64) ? 3200 : 6400;
        float p = phi[base + idx];
        float c, s;
        sincosf(0.5f * p, &s, &c);
        g_encphi[idx] = make_float2(c, s);
    }
}

// ---------------- segment layer step (register/shuffle state machine) ----------------
__device__ __forceinline__ void seg_step(float2 amp[8], const float4 uvL[8],
                                         const float sgn[8], int lane, bool docz) {
    #pragma unroll
    for (int q = 0; q < 5; q++) {
        float4 uv = uvL[q];
        int b = 4 - q;
        int mybit = (lane >> b) & 1;
        float mai = mybit ? -uv.y : uv.y;
        float mbr = mybit ?  uv.z : -uv.z;
        ull Ap = pack2(uv.x, mai),  An = pack2(-mai, uv.x);
        ull Bp = pack2(mbr, uv.w),  Bn = pack2(-uv.w, mbr);
        #pragma unroll
        for (int j = 0; j < 8; j++) {
            float pr = __shfl_xor_sync(0xffffffffu, amp[j].x, 1 << b);
            float pi = __shfl_xor_sync(0xffffffffu, amp[j].y, 1 << b);
            ull acc = 0ull;
            ffma2(acc, pack2(amp[j].x, amp[j].x), Ap);
            ffma2(acc, pack2(amp[j].y, amp[j].y), An);
            ffma2(acc, pack2(pr, pr), Bp);
            ffma2(acc, pack2(pi, pi), Bn);
            amp[j] = unpack2(acc);
        }
    }
    #pragma unroll
    for (int q = 5; q < 8; q++) {
        float4 uv = uvL[q];
        int p = 7 - q;
        ull A00p = pack2( uv.x,  uv.y), A00n = pack2(-uv.y,  uv.x);
        ull A01p = pack2(-uv.z,  uv.w), A01n = pack2(-uv.w, -uv.z);
        ull A10p = pack2( uv.z,  uv.w), A10n = pack2(-uv.w,  uv.z);
        ull A11p = pack2( uv.x, -uv.y), A11n = pack2( uv.y,  uv.x);
        #pragma unroll
        for (int t = 0; t < 4; t++) {
            int lowm = (1 << p) - 1;
            int j0 = ((t & ~lowm) << 1) | (t & lowm);
            int j1 = j0 | (1 << p);
            float2 a0 = amp[j0], a1 = amp[j1];
            ull sx0 = pack2(a0.x, a0.x), sy0 = pack2(a0.y, a0.y);
            ull sx1 = pack2(a1.x, a1.x), sy1 = pack2(a1.y, a1.y);
            ull acc0 = 0ull, acc1 = 0ull;
            ffma2(acc0, sx0, A00p); ffma2(acc0, sy0, A00n);
            ffma2(acc0, sx1, A01p); ffma2(acc0, sy1, A01n);
            ffma2(acc1, sx0, A10p); ffma2(acc1, sy0, A10n);
            ffma2(acc1, sx1, A11p); ffma2(acc1, sy1, A11n);
            amp[j0] = unpack2(acc0);
            amp[j1] = unpack2(acc1);
        }
    }
    if (docz) {
        #pragma unroll
        for (int j = 0; j < 8; j++) { amp[j].x *= sgn[j]; amp[j].y *= sgn[j]; }
    }
}

// ---------------- K1: build segment columns + v0 (exact R8 layout) ----------------
__global__ void __launch_bounds__(256) k_build() {
    int gw = blockIdx.x * 8 + (threadIdx.x >> 5);
    if (gw >= 1025) return;
    int lane = threadIdx.x & 31;

    int Lbase, NL, col;
    bool czlast;
    float2* outp;
    float initv;
    if (gw < 1024) {
        int s = gw >> 8;
        col = gw & 255;
        Lbase = 200 + s * 100;        // s=0:200, 1:300, 2:400, 3:500
        NL = 100;
        czlast = (s != 3);            // only U3-seg2's final layer has no CZ
        outp = &g_S[s][col * NS];
        initv = (s == 0 || s == 2) ? czsign(col) : 1.0f;  // fold encode-Dcz into seg1 init
    } else {
        Lbase = 0; NL = DEPTH; czlast = true; col = 0; outp = g_v0; initv = 1.0f;
    }

    float2 amp[8];
    float  sgn[8];
    #pragma unroll
    for (int j = 0; j < 8; j++) {
        int n = lane * 8 + j;
        amp[j] = (n == col) ? make_float2(initv, 0.f) : make_float2(0.f, 0.f);
        sgn[j] = czsign(n);
    }

    float4 uvA[8], uvB[8];
    #pragma unroll
    for (int q = 0; q < 8; q++) uvA[q] = g_uv[Lbase * 8 + q];

    for (int l = 0; l < NL; l += 2) {
        #pragma unroll
        for (int q = 0; q < 8; q++) uvB[q] = g_uv[(Lbase + l + 1) * 8 + q];
        seg_step(amp, uvA, sgn, lane, (l < NL - 1) || czlast);
        if (l + 2 < NL) {
            #pragma unroll
            for (int q = 0; q < 8; q++) uvA[q] = g_uv[(Lbase + l + 2) * 8 + q];
        }
        seg_step(amp, uvB, sgn, lane, (l + 1 < NL - 1) || czlast);
    }

    float4* o4 = reinterpret_cast<float4*>(outp);
    #pragma unroll
    for (int jj = 0; jj < 4; jj++)
        o4[lane * 4 + jj] = make_float4(amp[2 * jj].x, amp[2 * jj].y,
                                        amp[2 * jj + 1].x, amp[2 * jj + 1].y);
}

// ---------------- K1b: combine segments  U' = S2 * S1 -> g_WT [k][m] complex ----------------
__global__ void __launch_bounds__(256) k_comb() {
    extern __shared__ float smraw[];
    float2* sPsi = (float2*)smraw;            // NS * NTP
    float2* sA2  = sPsi + NS * NTP;           // 2 x 2048 ping-pong

    int tid = threadIdx.x, lane = tid & 31, warp = tid >> 5;
    int g = blockIdx.x >> 3;
    int cbase = (blockIdx.x & 7) * 32;
    const float2* __restrict__ S1 = g_S[2 * g];
    const float2* __restrict__ AT = g_S[2 * g + 1];   // AT[k*256+m] = S2[m][k]
    float2* W = g_WT[g];

    for (int idx = tid; idx < NS * NT; idx += 256) {
        int k = idx & 255, b = idx >> 8;
        sPsi[k * NTP + b] = S1[(cbase + b) * NS + k];
    }
    float2 pre[8];
    #pragma unroll
    for (int r = 0; r < 8; r++) pre[r] = AT[tid + r * 256];
    __syncthreads();

    int mh = warp >> 2, bo = warp & 3;
    int mbase = mh * 128 + lane * 4;
    ull acc[4][8];
    #pragma unroll
    for (int r = 0; r < 4; r++)
        #pragma unroll
        for (int j = 0; j < 8; j++) acc[r][j] = 0ull;

    for (int kc = 0; kc < 32; kc++) {
        float2* buf = sA2 + (kc & 1) * 2048;
        #pragma unroll
        for (int r = 0; r < 8; r++) buf[tid + r * 256] = pre[r];
        if (kc + 1 < 32) {
            #pragma unroll
            for (int r = 0; r < 8; r++) pre[r] = AT[(kc + 1) * 2048 + tid + r * 256];
        }
        __syncthreads();
        #pragma unroll
        for (int kk = 0; kk < 8; kk++) {
            int k = kc * 8 + kk;
            float4 a01 = *reinterpret_cast<const float4*>(&buf[kk * 256 + mbase]);
            float4 a23 = *reinterpret_cast<const float4*>(&buf[kk * 256 + mbase + 2]);
            ull ap[4], as_[4];
            ap[0] = pack2(a01.x, a01.y); as_[0] = pack2(a01.y, a01.x);
            ap[1] = pack2(a01.z, a01.w); as_[1] = pack2(a01.w, a01.z);
            ap[2] = pack2(a23.x, a23.y); as_[2] = pack2(a23.y, a23.x);
            ap[3] = pack2(a23.z, a23.w); as_[3] = pack2(a23.w, a23.z);
            #pragma unroll
            for (int j = 0; j < 8; j++) {
                float2 bv = sPsi[k * NTP + bo * 8 + j];
                ull Br = pack2(bv.x, bv.x);
                ull Bn = pack2(-bv.y, bv.y);
                #pragma unroll
                for (int r = 0; r < 4; r++) {
                    ffma2(acc[r][j], ap[r], Br);
                    ffma2(acc[r][j], as_[r], Bn);
                }
            }
        }
        __syncthreads();
    }
    #pragma unroll
    for (int j = 0; j < 8; j++) {
        int c = cbase + bo * 8 + j;
        float2 e0 = unpack2(acc[0][j]), e1 = unpack2(acc[1][j]);
        float2 e2 = unpack2(acc[2][j]), e3 = unpack2(acc[3][j]);
        *reinterpret_cast<float4*>(&W[c * NS + mbase])     = make_float4(e0.x, e0.y, e1.x, e1.y);
        *reinterpret_cast<float4*>(&W[c * NS + mbase + 2]) = make_float4(e2.x, e2.y, e3.x, e3.y);
    }
}

// ---------------- K2: fused per-batch pipeline ----------------
__device__ __forceinline__ void su2_mul(float& Eur, float& Eui, float& Evr, float& Evi,
                                        float gur, float gui, float gvr, float gvi) {
    float ur = gur * Eur - gui * Eui - (gvr * Evr + gvi * Evi);
    float ui = gur * Eui + gui * Eur - (gvr * Evi - gvi * Evr);
    float vr = gvr * Eur - gvi * Eui + (gur * Evr + gui * Evi);
    float vi = gvr * Eui + gvi * Eur + (gur * Evi - gui * Evr);
    Eur = ur; Eui = ui; Evr = vr; Evi = vi;
}

__device__ __forceinline__ float4 compose_E(const float* __restrict__ x, int bg,
                                            int xoff, int enc, int i) {
    float Eur = 1.f, Eui = 0.f, Evr = 0.f, Evi = 0.f;
    #pragma unroll
    for (int j = 0; j < 4; j++) {
        float2 p0 = g_encphi[enc * 64 + 8 * i + 2 * j];
        float2 p1 = g_encphi[enc * 64 + 8 * i + 2 * j + 1];
        float xv = x[(size_t)bg * NXF + xoff + 4 * i + j];
        float sx, cx;
        sincosf(0.5f * xv, &sx, &cx);
        if ((j & 1) == 0) {
            su2_mul(Eur, Eui, Evr, Evi, p0.x, 0.f, p0.y, 0.f);   // RY(p0)
            su2_mul(Eur, Eui, Evr, Evi, cx, 0.f, 0.f, -sx);      // RX(x)
            su2_mul(Eur, Eui, Evr, Evi, p1.x, 0.f, p1.y, 0.f);   // RY(p1)
        } else {
            su2_mul(Eur, Eui, Evr, Evi, p0.x, 0.f, 0.f, -p0.y);  // RX(p0)
            su2_mul(Eur, Eui, Evr, Evi, cx, 0.f, sx, 0.f);       // RY(x)
            su2_mul(Eur, Eui, Evr, Evi, p1.x, 0.f, 0.f, -p1.y);  // RX(p1)
        }
    }
    return make_float4(Eur, Eui, Evr, Evi);
}

// compose encode E for this thread's (q = tid>>5, b = tid&31) and write the
// 8 packed FFMA2 operand slots into sEp[(q*8+s)*32 + b].
__device__ __forceinline__ void compose_pack(const float* __restrict__ x, int bbase,
                                             int xoff, int enc, ull* sEp, int tid) {
    int b = tid & 31, q = tid >> 5;
    float4 E = compose_E(x, bbase + b, xoff, enc, q);
    ull* dst = sEp + q * 8 * 32 + b;
    dst[0 * 32] = pack2( E.x,  E.y);   // x a0.x -> b0
    dst[1 * 32] = pack2(-E.y,  E.x);   // x a0.y -> b0
    dst[2 * 32] = pack2(-E.z,  E.w);   // x a1.x -> b0
    dst[3 * 32] = pack2(-E.w, -E.z);   // x a1.y -> b0
    dst[4 * 32] = pack2( E.z,  E.w);   // x a0.x -> b1
    dst[5 * 32] = pack2(-E.w,  E.z);   // x a0.y -> b1
    dst[6 * 32] = pack2( E.x, -E.y);   // x a1.x -> b1
    dst[7 * 32] = pack2( E.y,  E.x);   // x a1.y -> b1
}

// one packed gate on pair (u,v) given splats and 8 packed operand slots
__device__ __forceinline__ void gate_p(ull& outu, ull& outv,
                                       ull xu, ull yu, ull xv, ull yv,
                                       const ull G[8]) {
    ull au = 0ull, av = 0ull;
    ffma2(au, xu, G[0]); ffma2(au, yu, G[1]);
    ffma2(au, xv, G[2]); ffma2(au, yv, G[3]);
    ffma2(av, xu, G[4]); ffma2(av, yu, G[5]);
    ffma2(av, xv, G[6]); ffma2(av, yv, G[7]);
    outu = au; outv = av;
}
__device__ __forceinline__ void splat_p(ull a, ull& sx, ull& sy) {
    float2 t = unpack2(a);
    sx = pack2(t.x, t.x);
    sy = pack2(t.y, t.y);
}

// 2-qubit-fused packed gate application: 4 passes; each thread owns 4 amps
// spanning bits (ph = 7-2i, pl = 6-2i) per iteration; both gates in registers.
__device__ __forceinline__ void apply_gates_p2(float2* sPsi, const ull* sEp, int tid) {
    int b = tid & 31;
    #pragma unroll
    for (int i = 0; i < 4; i++) {
        ull Gh[8], Gl[8];
        #pragma unroll
        for (int s = 0; s < 8; s++) {
            Gh[s] = sEp[((2 * i) * 8 + s) * 32 + b];       // qubit 2i   (bit ph)
            Gl[s] = sEp[((2 * i + 1) * 8 + s) * 32 + b];   // qubit 2i+1 (bit pl)
        }
        int pl = 6 - 2 * i;
        int low = (1 << pl) - 1;
        #pragma unroll
        for (int it = 0; it < 8; it++) {
            int g = (tid >> 5) + it * 8;                   // 0..63
            int base = ((g & ~low) << 2) | (g & low);
            int n0 = base;
            int n1 = base | (1 << pl);
            int n2 = base | (2 << pl);
            int n3 = base | (3 << pl);
            float2 a0 = sPsi[n0 * NTP + b];
            float2 a1 = sPsi[n1 * NTP + b];
            float2 a2 = sPsi[n2 * NTP + b];
            float2 a3 = sPsi[n3 * NTP + b];
            ull x0 = pack2(a0.x, a0.x), y0 = pack2(a0.y, a0.y);
            ull x1 = pack2(a1.x, a1.x), y1 = pack2(a1.y, a1.y);
            ull x2 = pack2(a2.x, a2.x), y2 = pack2(a2.y, a2.y);
            ull x3 = pack2(a3.x, a3.x), y3 = pack2(a3.y, a3.y);
            // qubit 2i (hi bit): pairs (0,2), (1,3)
            ull c0, c1, c2, c3;
            gate_p(c0, c2, x0, y0, x2, y2, Gh);
            gate_p(c1, c3, x1, y1, x3, y3, Gh);
            // re-splat
            ull u0x, u0y, u1x, u1y, u2x, u2y, u3x, u3y;
            splat_p(c0, u0x, u0y); splat_p(c1, u1x, u1y);
            splat_p(c2, u2x, u2y); splat_p(c3, u3x, u3y);
            // qubit 2i+1 (lo bit): pairs (0,1), (2,3)
            ull d0, d1, d2, d3;
            gate_p(d0, d1, u0x, u0y, u1x, u1y, Gl);
            gate_p(d2, d3, u2x, u2y, u3x, u3y, Gl);
            *reinterpret_cast<ull*>(&sPsi[n0 * NTP + b]) = d0;
            *reinterpret_cast<ull*>(&sPsi[n1 * NTP + b]) = d1;
            *reinterpret_cast<ull*>(&sPsi[n2 * NTP + b]) = d2;
            *reinterpret_cast<ull*>(&sPsi[n3 * NTP + b]) = d3;
        }
        __syncthreads();
    }
}

// in-place complex GEMM, packed f32x2 FMAs, single-buffer A staging:
//   sPsi[m][b] = sum_k AT[k][m] * sPsi[k][b]
__device__ __forceinline__ void do_gemm(float2* sPsi, float2* sA2,
                                        const float2* __restrict__ AT,
                                        float2 pre[8],
                                        int tid, int lane, int warp) {
    int mh = warp >> 2;            // m-half:   m = mh*128 + lane*4 + rr
    int bo = warp & 3;             // b-octet:  b = bo*8 + j
    int mbase = mh * 128 + lane * 4;
    ull acc[4][8];
    #pragma unroll
    for (int r = 0; r < 4; r++)
        #pragma unroll
        for (int j = 0; j < 8; j++) acc[r][j] = 0ull;

    for (int kc = 0; kc < 32; kc++) {
        __syncthreads();  // previous compute done reading sA2
        #pragma unroll
        for (int r = 0; r < 8; r++) sA2[tid + r * 256] = pre[r];
        __syncthreads();
        if (kc + 1 < 32) {
            #pragma unroll
            for (int r = 0; r < 8; r++) pre[r] = AT[(kc + 1) * 2048 + tid + r * 256];
        }
        #pragma unroll
        for (int kk = 0; kk < 8; kk++) {
            int k = kc * 8 + kk;
            float4 a01 = *reinterpret_cast<const float4*>(&sA2[kk * 256 + mbase]);
            float4 a23 = *reinterpret_cast<const float4*>(&sA2[kk * 256 + mbase + 2]);
            ull ap[4], as_[4];
            ap[0] = pack2(a01.x, a01.y); as_[0] = pack2(a01.y, a01.x);
            ap[1] = pack2(a01.z, a01.w); as_[1] = pack2(a01.w, a01.z);
            ap[2] = pack2(a23.x, a23.y); as_[2] = pack2(a23.y, a23.x);
            ap[3] = pack2(a23.z, a23.w); as_[3] = pack2(a23.w, a23.z);
            #pragma unroll
            for (int j = 0; j < 8; j++) {
                float2 bv = sPsi[k * NTP + bo * 8 + j];
                ull Br = pack2(bv.x, bv.x);
                ull Bn = pack2(-bv.y, bv.y);
                #pragma unroll
                for (int r = 0; r < 4; r++) {
                    ffma2(acc[r][j], ap[r], Br);    // (a.r, a.i) * (b.r, b.r)
                    ffma2(acc[r][j], as_[r], Bn);   // (a.i, a.r) * (-b.i, b.i)
                }
            }
        }
    }
    __syncthreads();  // all reads of sPsi done before overwrite
    #pragma unroll
    for (int r = 0; r < 4; r++)
        #pragma unroll
        for (int j = 0; j < 8; j++)
            *reinterpret_cast<ull*>(&sPsi[(mbase + r) * NTP + bo * 8 + j]) = acc[r][j];
    __syncthreads();
}

__global__ void __launch_bounds__(256, 2) k_main(const float* __restrict__ x,
                                                 float* __restrict__ out) {
    extern __shared__ float smraw[];
    float2* sPsi = (float2*)smraw;              // NS * NTP float2    (67584 B)
    float2* sA2  = sPsi + NS * NTP;             // 2048 float2        (16384 B)
    ull*    sEp  = (ull*)(sA2 + 2048);          // 8*8*32 ull         (16384 B)

    int tid = threadIdx.x;
    int lane = tid & 31, warp = tid >> 5;       // 8 warps
    int bbase = blockIdx.x * NT;

    // ---- prefetch first A-chunk of U2' (hidden behind encode compute) ----
    float2 pre[8];
    #pragma unroll
    for (int r = 0; r < 8; r++) pre[r] = g_WT[0][tid + r * 256];

    // ---- E1 compose + pack ----
    compose_pack(x, bbase, 0, 0, sEp, tid);

    // ---- init Psi = v0 (broadcast over batches) ----
    for (int idx = tid; idx < NS * NT; idx += 256) {
        int b = idx & (NT - 1), amp = idx >> 5;
        sPsi[amp * NTP + b] = g_v0[amp];
    }
    __syncthreads();

    apply_gates_p2(sPsi, sEp, tid);             // encode 1 (CZ folded into U2')
    do_gemm(sPsi, sA2, g_WT[0], pre, tid, lane, warp);

    // ---- prefetch first A-chunk of U3', then E2 compose + pack ----
    #pragma unroll
    for (int r = 0; r < 8; r++) pre[r] = g_WT[1][tid + r * 256];
    compose_pack(x, bbase, 32, 1, sEp, tid);
    __syncthreads();

    apply_gates_p2(sPsi, sEp, tid);             // encode 2 (CZ folded into U3')
    do_gemm(sPsi, sA2, g_WT[1], pre, tid, lane, warp);

    // ---- measurement: warp w handles batches w*4..w*4+3 ----
    for (int j = 0; j < 4; j++) {
        int b = warp * 4 + j;
        float sums[8];
        #pragma unroll
        for (int k = 0; k < 8; k++) sums[k] = 0.f;
        #pragma unroll
        for (int r = 0; r < 8; r++) {
            int m = lane + 32 * r;
            float2 ps = sPsi[m * NTP + b];
            float p2 = ps.x * ps.x + ps.y * ps.y;
            sums[4] += (m & 128) ? -p2 : p2;   // Z q0
            sums[5] += (m & 64)  ? -p2 : p2;   // Z q1
            sums[6] += (m & 32)  ? -p2 : p2;   // Z q2
            sums[7] += (m & 16)  ? -p2 : p2;   // Z q3
            float2 q0 = sPsi[(m ^ 128) * NTP + b];
            sums[0] += ps.x * q0.x + ps.y * q0.y;   // X q0
            float2 q1 = sPsi[(m ^ 64) * NTP + b];
            sums[1] += ps.x * q1.x + ps.y * q1.y;   // X q1
            float2 q2 = sPsi[(m ^ 32) * NTP + b];
            sums[2] += ps.x * q2.x + ps.y * q2.y;   // X q2
            float2 q3 = sPsi[(m ^ 16) * NTP + b];
            sums[3] += ps.x * q3.x + ps.y * q3.y;   // X q3
        }
        #pragma unroll
        for (int off = 16; off; off >>= 1) {
            #pragma unroll
            for (int k = 0; k < 8; k++)
                sums[k] += __shfl_xor_sync(0xffffffffu, sums[k], off);
        }
        if (lane < 8) out[(size_t)(bbase + b) * 8 + lane] = sums[lane];
    }
}

// ---------------- launch ----------------
extern "C" void kernel_launch(void* const* d_in, const int* in_sizes, int n_in,
                              void* d_out, int out_size) {
    const float* x   = (const float*)d_in[0];
    const float* phi = (const float*)d_in[1];
    float* out = (float*)d_out;

    const size_t smem_c = (size_t)(NS * NTP) * sizeof(float2)   // 67584
                        + (size_t)(2 * 2048) * sizeof(float2);  // 32768
    const size_t smem_m = (size_t)(NS * NTP) * sizeof(float2)   // 67584
                        + (size_t)2048 * sizeof(float2)         // 16384
                        + (size_t)2048 * sizeof(ull);           // 16384
    cudaFuncSetAttribute(k_comb, cudaFuncAttributeMaxDynamicSharedMemorySize, (int)smem_c);
    cudaFuncSetAttribute(k_main, cudaFuncAttributeMaxDynamicSharedMemorySize, (int)smem_m);

    k_tables<<<20, 256>>>(phi);
    k_build<<<129, 256>>>();
    k_comb<<<16, 256, smem_c>>>();
    k_main<<<NBLK, 256, smem_m>>>(x, out);
}